// round 14
// baseline (speedup 1.0000x reference)
#include <cuda_runtime.h>
#include <cuda_fp16.h>
#include <math.h>
#include <stdint.h>

#define NROI 512
#define NPOS 128
#define NCLS 81
#define KDIM 12544
#define HID  1024
#define NCLSP 128
#define NWROWS 512

// ---------------- scratch ----------------
__device__ __align__(256) __half g_featT[17408000];
__device__ __align__(256) __half g_x[NROI * KDIM];
__device__ __align__(256) __half g_W1T[HID * KDIM];
__device__ __align__(256) __half g_W2T[HID * HID];
__device__ __align__(256) __half g_WhT[NWROWS * HID];
__device__ float g_bh[NWROWS];
__device__ __align__(256) __half g_h1[NROI * HID];
__device__ __align__(256) __half g_h2[NROI * HID];
__device__ float g_head[NROI * NCLSP];
__device__ float g_locp4[NROI * 4];
__device__ float g_part[8 * NROI * HID];

// ---------------- helpers ----------------
__device__ __forceinline__ uint32_t smem_u32(const void* p) {
    uint32_t a;
    asm("{ .reg .u64 t; cvta.to.shared.u64 t, %1; cvt.u32.u64 %0, t; }" : "=r"(a) : "l"(p));
    return a;
}
#define CP_ASYNC16(dst, src) asm volatile("cp.async.cg.shared.global [%0], [%1], 16;" :: "r"(dst), "l"(src))
#define CP_COMMIT() asm volatile("cp.async.commit_group;" ::: "memory")
#define CP_WAIT(n)  asm volatile("cp.async.wait_group %0;" :: "n"(n) : "memory")

#define LDSM_X4(r0, r1, r2, r3, a) \
    asm volatile("ldmatrix.sync.aligned.m8n8.x4.shared.b16 {%0,%1,%2,%3}, [%4];" \
        : "=r"(r0), "=r"(r1), "=r"(r2), "=r"(r3) : "r"(a))

#define MMA16816(d, a, b0, b1) \
    asm volatile("mma.sync.aligned.m16n8k16.row.col.f32.f16.f16.f32 " \
        "{%0,%1,%2,%3}, {%4,%5,%6,%7}, {%8,%9}, {%0,%1,%2,%3};" \
        : "+f"((d)[0]), "+f"((d)[1]), "+f"((d)[2]), "+f"((d)[3]) \
        : "r"((a)[0]), "r"((a)[1]), "r"((a)[2]), "r"((a)[3]), "r"(b0), "r"(b1))

// ============ feature transpose: 2125 blocks ============
__global__ void __launch_bounds__(256) prep_feat(
        const float* __restrict__ P2, const float* __restrict__ P3,
        const float* __restrict__ P4, const float* __restrict__ P5,
        __half* __restrict__ featT) {
    __shared__ __align__(16) __half2 s2[32][132];
    int b = blockIdx.x;
    int w = threadIdx.x >> 5, l = threadIdx.x & 31;
    int lv, pt;
    if (b < 1600)      { lv = 0; pt = b; }
    else if (b < 2000) { lv = 1; pt = b - 1600; }
    else if (b < 2100) { lv = 2; pt = b - 2000; }
    else               { lv = 3; pt = b - 2100; }
    const int HWs[4]   = {51200, 12800, 3200, 800};
    const int bases[4] = {0, 13107200, 16384000, 17203200};
    const float* srcs[4] = {P2, P3, P4, P5};
    int HW = HWs[lv];
    const float* src = srcs[lv];
    __half* dst = featT + bases[lv];
    int p0 = pt * 32;
    #pragma unroll
    for (int m = 0; m < 4; m++) {
        int cp0 = w * 16 + m * 4;
        __half2 v[4];
        #pragma unroll
        for (int q = 0; q < 4; q++) {
            int c = 2 * (cp0 + q);
            float a = src[(size_t)c * HW + p0 + l];
            float bb = src[(size_t)(c + 1) * HW + p0 + l];
            v[q] = __floats2half2_rn(a, bb);
        }
        *(uint4*)&s2[l][cp0] = *(uint4*)v;
    }
    __syncthreads();
    #pragma unroll
    for (int j = 0; j < 4; j++) {
        int idx = j * 256 + threadIdx.x;
        int pos = idx >> 5, seg = idx & 31;
        uint4 val = *(uint4*)&s2[pos][seg * 4];
        *(uint4*)(dst + (size_t)(p0 + pos) * 256 + seg * 8) = val;
    }
}

// ============ weight prep: 3744 blocks ============
__global__ void __launch_bounds__(256) prep_w(
        const float* __restrict__ W1, const float* __restrict__ W2,
        const float* __restrict__ Wcls, const float* __restrict__ Wloc,
        const float* __restrict__ bcls, const float* __restrict__ bloc,
        __half* __restrict__ W1T, __half* __restrict__ W2T,
        __half* __restrict__ WhT, float* __restrict__ bh) {
    __shared__ __align__(16) __half2 s2[32][132];
    int b = blockIdx.x;
    int w = threadIdx.x >> 5, l = threadIdx.x & 31;

    if (b < 1568) {
        int k0 = (b % 49) * 256;
        int j0 = (b / 49) * 32;
        #pragma unroll
        for (int m = 0; m < 4; m++) {
            int cp0 = w * 16 + m * 4;
            __half2 v[4];
            #pragma unroll
            for (int q = 0; q < 4; q++) {
                int ka = k0 + 2 * (cp0 + q), kb = ka + 1;
                int ra = (ka & 255) * 49 + (ka >> 8);
                int rb = (kb & 255) * 49 + (kb >> 8);
                float a = W1[(size_t)ra * HID + j0 + l];
                float bb = W1[(size_t)rb * HID + j0 + l];
                v[q] = __floats2half2_rn(a, bb);
            }
            *(uint4*)&s2[l][cp0] = *(uint4*)v;
        }
        __syncthreads();
        #pragma unroll
        for (int j = 0; j < 4; j++) {
            int idx = j * 256 + threadIdx.x;
            int jr = idx >> 5, seg = idx & 31;
            uint4 val = *(uint4*)&s2[jr][seg * 4];
            *(uint4*)(W1T + (size_t)(j0 + jr) * KDIM + k0 + seg * 8) = val;
        }
    } else if (b < 1696) {
        int lb = b - 1568;
        int k0 = (lb & 3) * 256;
        int j0 = (lb >> 2) * 32;
        #pragma unroll
        for (int m = 0; m < 4; m++) {
            int cp0 = w * 16 + m * 4;
            __half2 v[4];
            #pragma unroll
            for (int q = 0; q < 4; q++) {
                int ka = k0 + 2 * (cp0 + q);
                float a = W2[(size_t)ka * HID + j0 + l];
                float bb = W2[(size_t)(ka + 1) * HID + j0 + l];
                v[q] = __floats2half2_rn(a, bb);
            }
            *(uint4*)&s2[l][cp0] = *(uint4*)v;
        }
        __syncthreads();
        #pragma unroll
        for (int j = 0; j < 4; j++) {
            int idx = j * 256 + threadIdx.x;
            int jr = idx >> 5, seg = idx & 31;
            uint4 val = *(uint4*)&s2[jr][seg * 4];
            *(uint4*)(W2T + (size_t)(j0 + jr) * HID + k0 + seg * 8) = val;
        }
    } else {
        int lb = b - 1696;
        int j = lb >> 2;
        int k = (lb & 3) * 256 + threadIdx.x;
        float v = 0.0f;
        if (j < NCLSP) {
            if (j < NCLS) v = Wcls[(size_t)k * NCLS + j];
        } else {
            int jj = j - NCLSP;
            if (jj < NCLS * 4) v = Wloc[(size_t)k * (NCLS * 4) + jj];
        }
        WhT[(size_t)j * HID + k] = __float2half(v);
        if ((lb & 3) == 0 && threadIdx.x == 0) {
            float bv = 0.0f;
            if (j < NCLSP) { if (j < NCLS) bv = bcls[j]; }
            else { int jj = j - NCLSP; if (jj < NCLS * 4) bv = bloc[jj]; }
            bh[j] = bv;
        }
    }
}

// ============ RoIAlign: 512 threads ============
__global__ void __launch_bounds__(512) pool_v3(const float* __restrict__ rois,
                                               const __half2* __restrict__ featT2,
                                               __half2* __restrict__ xout2) {
    int n = blockIdx.x;
    int cidx = threadIdx.x & 127;
    int h = threadIdx.x >> 7;

    float rx1 = rois[n * 4 + 0], ry1 = rois[n * 4 + 1];
    float rx2 = rois[n * 4 + 2], ry2 = rois[n * 4 + 3];
    float area = (rx2 - rx1 + 1.0f) * (ry2 - ry1 + 1.0f);
    float lf = floorf(4.0f + log2f(sqrtf(area) / 224.0f));
    lf = fminf(fmaxf(lf, 2.0f), 5.0f);
    int lv = (int)lf - 2;

    const int   Hs[4]     = {200, 100, 50, 25};
    const int   Ws[4]     = {256, 128, 64, 32};
    const int   bases2[4] = {0, 6553600, 8192000, 8601600};
    const float scl[4]    = {0.25f, 0.125f, 0.0625f, 0.03125f};

    int H = Hs[lv], W = Ws[lv];
    const __half2* ft = featT2 + bases2[lv];
    float scale = scl[lv];

    float x1 = rx1 * scale, y1 = ry1 * scale;
    float x2 = rx2 * scale, y2 = ry2 * scale;
    float bw = fmaxf(x2 - x1, 1.0f) / 7.0f;
    float bh = fmaxf(y2 - y1, 1.0f) / 7.0f;

    for (int bin = h; bin < 49; bin += 4) {
        int oy = bin / 7, ox = bin % 7;
        float2 acc = make_float2(0.0f, 0.0f);
        #pragma unroll
        for (int sy = 0; sy < 2; sy++) {
            #pragma unroll
            for (int sx = 0; sx < 2; sx++) {
                float px = x1 + ((float)ox + ((float)sx + 0.5f) * 0.5f) * bw;
                float py = y1 + ((float)oy + ((float)sy + 0.5f) * 0.5f) * bh;
                bool valid = (px > -1.0f) && (px < (float)W) && (py > -1.0f) && (py < (float)H);
                if (!valid) continue;
                float xx = fminf(fmaxf(px, 0.0f), (float)(W - 1));
                float yy = fminf(fmaxf(py, 0.0f), (float)(H - 1));
                float x0f = floorf(xx), y0f = floorf(yy);
                float lx = xx - x0f, ly = yy - y0f;
                int x0 = (int)x0f, y0 = (int)y0f;
                int x1i = min(x0 + 1, W - 1), y1i = min(y0 + 1, H - 1);
                const __half2* r0 = ft + (size_t)(y0  * W) * 128;
                const __half2* r1 = ft + (size_t)(y1i * W) * 128;
                float w00 = (1.0f - ly) * (1.0f - lx);
                float w01 = (1.0f - ly) * lx;
                float w10 = ly * (1.0f - lx);
                float w11 = ly * lx;
                float2 v00 = __half22float2(r0[x0  * 128 + cidx]);
                float2 v01 = __half22float2(r0[x1i * 128 + cidx]);
                float2 v10 = __half22float2(r1[x0  * 128 + cidx]);
                float2 v11 = __half22float2(r1[x1i * 128 + cidx]);
                acc.x += w00 * v00.x + w01 * v01.x + w10 * v10.x + w11 * v11.x;
                acc.y += w00 * v00.y + w01 * v01.y + w10 * v10.y + w11 * v11.y;
            }
        }
        xout2[(size_t)n * (KDIM / 2) + bin * 128 + cidx] =
            __floats2half2_rn(acc.x * 0.25f, acc.y * 0.25f);
    }
}

// ---------------- HMMA GEMM, 4-stage pipeline ----------------
__global__ void __launch_bounds__(256) gemm_hmma(const __half* __restrict__ A,
                                                 const __half* __restrict__ Bt,
                                                 float* __restrict__ part,
                                                 int N, int Krow, int ksplit) {
    __shared__ __align__(128) __half As[4][128 * 32];
    __shared__ __align__(128) __half Bs[4][64 * 32];

    int tid = threadIdx.x, wid = tid >> 5, lane = tid & 31;
    int m0 = blockIdx.y * 128, n0 = blockIdx.x * 64;
    int z = blockIdx.z;
    int kb0 = z * ksplit;
    int wm = (wid & 3) * 32;
    int wn = (wid >> 2) * 32;

    uint32_t sA = smem_u32(As), sB = smem_u32(Bs);
    int nch = ksplit >> 5;

    int ldr = tid >> 2, ldc = tid & 3;
    int sw0 = (ldc ^ ((ldr >> 1) & 3));
    int row1 = ldr + 64;
    int sw1 = (ldc ^ ((row1 >> 1) & 3));
    uint32_t stA0 = sA + (ldr * 32 + sw0 * 8) * 2;
    uint32_t stA1 = sA + (row1 * 32 + sw1 * 8) * 2;
    uint32_t stB0 = sB + (ldr * 32 + sw0 * 8) * 2;
    const char* gA0 = (const char*)(A + (size_t)(m0 + ldr) * Krow + kb0) + ldc * 16;
    const char* gA1 = (const char*)(A + (size_t)(m0 + row1) * Krow + kb0) + ldc * 16;
    const char* gB0 = (const char*)(Bt + (size_t)(n0 + ldr) * Krow + kb0) + ldc * 16;

    #pragma unroll
    for (int p = 0; p < 3; p++) {
        int koff = p << 6;
        CP_ASYNC16(stA0 + p * 8192, gA0 + koff);
        CP_ASYNC16(stA1 + p * 8192, gA1 + koff);
        CP_ASYNC16(stB0 + p * 4096, gB0 + koff);
        CP_COMMIT();
    }

    float acc[2][4][4];
    #pragma unroll
    for (int mi = 0; mi < 2; mi++)
        #pragma unroll
        for (int ni = 0; ni < 4; ni++)
            #pragma unroll
            for (int j = 0; j < 4; j++) acc[mi][ni][j] = 0.0f;

    for (int k = 0; k < nch; k++) {
        if (k + 3 < nch) { CP_WAIT(2); } else { CP_WAIT(0); }
        __syncthreads();
        if (k + 3 < nch) {
            int p = (k + 3) & 3;
            int koff = (k + 3) << 6;
            CP_ASYNC16(stA0 + p * 8192, gA0 + koff);
            CP_ASYNC16(stA1 + p * 8192, gA1 + koff);
            CP_ASYNC16(stB0 + p * 4096, gB0 + koff);
            CP_COMMIT();
        }
        int buf = k & 3;

        uint32_t bf[4][4];
        #pragma unroll
        for (int ni = 0; ni < 4; ni++) {
            int row = wn + ni * 8 + (lane & 7);
            int ch = lane >> 3;
            int sw = ch ^ ((row >> 1) & 3);
            uint32_t a = sB + (buf * 2048 + row * 32 + sw * 8) * 2;
            LDSM_X4(bf[ni][0], bf[ni][1], bf[ni][2], bf[ni][3], a);
        }
        #pragma unroll
        for (int s = 0; s < 2; s++) {
            uint32_t af[2][4];
            #pragma unroll
            for (int mi = 0; mi < 2; mi++) {
                int row = wm + mi * 16 + (lane & 15);
                int ch = 2 * s + (lane >> 4);
                int sw = ch ^ ((row >> 1) & 3);
                uint32_t a = sA + (buf * 4096 + row * 32 + sw * 8) * 2;
                LDSM_X4(af[mi][0], af[mi][1], af[mi][2], af[mi][3], a);
            }
            #pragma unroll
            for (int mi = 0; mi < 2; mi++)
                #pragma unroll
                for (int ni = 0; ni < 4; ni++)
                    MMA16816(acc[mi][ni], af[mi], bf[ni][2 * s], bf[ni][2 * s + 1]);
        }
    }

    float* out = part + (size_t)z * NROI * N;
    #pragma unroll
    for (int mi = 0; mi < 2; mi++) {
        #pragma unroll
        for (int ni = 0; ni < 4; ni++) {
            int m = m0 + wm + mi * 16 + (lane >> 2);
            int n = n0 + wn + ni * 8 + (lane & 3) * 2;
            out[(size_t)m * N + n]           = acc[mi][ni][0];
            out[(size_t)m * N + n + 1]       = acc[mi][ni][1];
            out[(size_t)(m + 8) * N + n]     = acc[mi][ni][2];
            out[(size_t)(m + 8) * N + n + 1] = acc[mi][ni][3];
        }
    }
}

// ---------------- head GEMM: no split, fused bias ----------------
__global__ void __launch_bounds__(256) gemm_direct(const __half* __restrict__ A,
                                                   const __half* __restrict__ Bt,
                                                   const float* __restrict__ bias,
                                                   float* __restrict__ Cout,
                                                   int N, int Krow) {
    __shared__ __align__(128) __half As[4][128 * 32];
    __shared__ __align__(128) __half Bs[4][64 * 32];

    int tid = threadIdx.x, wid = tid >> 5, lane = tid & 31;
    int m0 = blockIdx.y * 128, n0 = blockIdx.x * 64;
    int wm = (wid & 3) * 32;
    int wn = (wid >> 2) * 32;

    uint32_t sA = smem_u32(As), sB = smem_u32(Bs);
    int nch = Krow >> 5;

    int ldr = tid >> 2, ldc = tid & 3;
    int sw0 = (ldc ^ ((ldr >> 1) & 3));
    int row1 = ldr + 64;
    int sw1 = (ldc ^ ((row1 >> 1) & 3));
    uint32_t stA0 = sA + (ldr * 32 + sw0 * 8) * 2;
    uint32_t stA1 = sA + (row1 * 32 + sw1 * 8) * 2;
    uint32_t stB0 = sB + (ldr * 32 + sw0 * 8) * 2;
    const char* gA0 = (const char*)(A + (size_t)(m0 + ldr) * Krow) + ldc * 16;
    const char* gA1 = (const char*)(A + (size_t)(m0 + row1) * Krow) + ldc * 16;
    const char* gB0 = (const char*)(Bt + (size_t)(n0 + ldr) * Krow) + ldc * 16;

    #pragma unroll
    for (int p = 0; p < 3; p++) {
        int koff = p << 6;
        CP_ASYNC16(stA0 + p * 8192, gA0 + koff);
        CP_ASYNC16(stA1 + p * 8192, gA1 + koff);
        CP_ASYNC16(stB0 + p * 4096, gB0 + koff);
        CP_COMMIT();
    }

    float acc[2][4][4];
    #pragma unroll
    for (int mi = 0; mi < 2; mi++)
        #pragma unroll
        for (int ni = 0; ni < 4; ni++)
            #pragma unroll
            for (int j = 0; j < 4; j++) acc[mi][ni][j] = 0.0f;

    for (int k = 0; k < nch; k++) {
        if (k + 3 < nch) { CP_WAIT(2); } else { CP_WAIT(0); }
        __syncthreads();
        if (k + 3 < nch) {
            int p = (k + 3) & 3;
            int koff = (k + 3) << 6;
            CP_ASYNC16(stA0 + p * 8192, gA0 + koff);
            CP_ASYNC16(stA1 + p * 8192, gA1 + koff);
            CP_ASYNC16(stB0 + p * 4096, gB0 + koff);
            CP_COMMIT();
        }
        int buf = k & 3;

        uint32_t bf[4][4];
        #pragma unroll
        for (int ni = 0; ni < 4; ni++) {
            int row = wn + ni * 8 + (lane & 7);
            int ch = lane >> 3;
            int sw = ch ^ ((row >> 1) & 3);
            uint32_t a = sB + (buf * 2048 + row * 32 + sw * 8) * 2;
            LDSM_X4(bf[ni][0], bf[ni][1], bf[ni][2], bf[ni][3], a);
        }
        #pragma unroll
        for (int s = 0; s < 2; s++) {
            uint32_t af[2][4];
            #pragma unroll
            for (int mi = 0; mi < 2; mi++) {
                int row = wm + mi * 16 + (lane & 15);
                int ch = 2 * s + (lane >> 4);
                int sw = ch ^ ((row >> 1) & 3);
                uint32_t a = sA + (buf * 4096 + row * 32 + sw * 8) * 2;
                LDSM_X4(af[mi][0], af[mi][1], af[mi][2], af[mi][3], a);
            }
            #pragma unroll
            for (int mi = 0; mi < 2; mi++)
                #pragma unroll
                for (int ni = 0; ni < 4; ni++)
                    MMA16816(acc[mi][ni], af[mi], bf[ni][2 * s], bf[ni][2 * s + 1]);
        }
    }

    #pragma unroll
    for (int mi = 0; mi < 2; mi++) {
        #pragma unroll
        for (int ni = 0; ni < 4; ni++) {
            int m = m0 + wm + mi * 16 + (lane >> 2);
            int n = n0 + wn + ni * 8 + (lane & 3) * 2;
            Cout[(size_t)m * N + n]           = acc[mi][ni][0] + bias[n];
            Cout[(size_t)m * N + n + 1]       = acc[mi][ni][1] + bias[n + 1];
            Cout[(size_t)(m + 8) * N + n]     = acc[mi][ni][2] + bias[n];
            Cout[(size_t)(m + 8) * N + n + 1] = acc[mi][ni][3] + bias[n + 1];
        }
    }
}

// ---------------- combine ----------------
template <int SPLIT, bool RELU, bool HOUT>
__global__ void combine_kernel(const float* __restrict__ part, const float* __restrict__ bias,
                               void* __restrict__ out, int N) {
    int q = blockIdx.x * 256 + threadIdx.x;
    int MN4 = NROI * N / 4;
    if (q >= MN4) return;
    int n = (q * 4) % N;
    float4 v = *(const float4*)(bias + n);
    #pragma unroll
    for (int z = 0; z < SPLIT; z++) {
        float4 p = *(const float4*)(part + (size_t)z * NROI * N + (size_t)q * 4);
        v.x += p.x; v.y += p.y; v.z += p.z; v.w += p.w;
    }
    if (RELU) {
        v.x = fmaxf(v.x, 0.0f); v.y = fmaxf(v.y, 0.0f);
        v.z = fmaxf(v.z, 0.0f); v.w = fmaxf(v.w, 0.0f);
    }
    if (HOUT) {
        __half2 h0 = __floats2half2_rn(v.x, v.y);
        __half2 h1 = __floats2half2_rn(v.z, v.w);
        ((uint2*)out)[q] = make_uint2(*(uint32_t*)&h0, *(uint32_t*)&h1);
    } else {
        ((float4*)out)[q] = v;
    }
}

// ---------------- loc select ----------------
__global__ void __launch_bounds__(128) loc_select_kernel(const __half* __restrict__ h2,
                                                         const __half* __restrict__ WhT,
                                                         const float* __restrict__ bh,
                                                         const int* __restrict__ label,
                                                         float* __restrict__ locp4) {
    int n = blockIdx.x;
    int j = threadIdx.x >> 5, lane = threadIdx.x & 31;
    int row = NCLSP + label[n] * 4 + j;
    const __half2* hv = (const __half2*)(h2 + (size_t)n * HID);
    const __half2* wv = (const __half2*)(WhT + (size_t)row * HID);
    float acc = 0.0f;
    #pragma unroll
    for (int i = 0; i < 16; i++) {
        float2 a = __half22float2(hv[lane + i * 32]);
        float2 b = __half22float2(wv[lane + i * 32]);
        acc += a.x * b.x + a.y * b.y;
    }
    #pragma unroll
    for (int off = 16; off > 0; off >>= 1)
        acc += __shfl_down_sync(0xFFFFFFFF, acc, off);
    if (lane == 0) locp4[n * 4 + j] = acc + bh[row];
}

// ---------------- loss ----------------
__global__ void loss_kernel(const float* __restrict__ head, const float* __restrict__ locp4,
                            const int* __restrict__ label, const float* __restrict__ loc,
                            float* __restrict__ out) {
    __shared__ float red[512];
    int n = threadIdx.x;
    const float* lg = head + (size_t)n * NCLSP;

    float mx = -1e30f;
    for (int j = 0; j < NCLS; j++) mx = fmaxf(mx, lg[j]);
    float s = 0.0f;
    for (int j = 0; j < NCLS; j++) s += expf(lg[j] - mx);
    int lab = label[n];
    float logp = lg[lab] - mx - logf(s);
    float contrib = -logp * (1.0f / (float)NROI);

    if (n < NPOS) {
        #pragma unroll
        for (int j = 0; j < 4; j++) {
            float d = fabsf(locp4[n * 4 + j] - loc[n * 4 + j]);
            float sl1 = (d < 1.0f) ? 0.5f * d * d : d - 0.5f;
            contrib += sl1 * (1.0f / (float)NROI);
        }
    }
    red[n] = contrib;
    __syncthreads();
    for (int stride = 256; stride > 0; stride >>= 1) {
        if (n < stride) red[n] += red[n + stride];
        __syncthreads();
    }
    if (n == 0) out[0] = red[0];
}

// ---------------- launch (two-stream fork/join) ----------------
extern "C" void kernel_launch(void* const* d_in, const int* in_sizes, int n_in,
                              void* d_out, int out_size) {
    const float* P2    = (const float*)d_in[0];
    const float* P3    = (const float*)d_in[1];
    const float* P4    = (const float*)d_in[2];
    const float* P5    = (const float*)d_in[3];
    const float* rois  = (const float*)d_in[4];
    const int*   label = (const int*)  d_in[5];
    const float* loc   = (const float*)d_in[6];
    const float* W1    = (const float*)d_in[7];
    const float* b1    = (const float*)d_in[8];
    const float* W2    = (const float*)d_in[9];
    const float* b2    = (const float*)d_in[10];
    const float* Wcls  = (const float*)d_in[11];
    const float* bcls  = (const float*)d_in[12];
    const float* Wloc  = (const float*)d_in[13];
    const float* bloc  = (const float*)d_in[14];
    float* out = (float*)d_out;

    __half *featT, *xb, *w1t, *w2t, *wht, *h1, *h2;
    float *bh, *head, *locp4, *partb;
    cudaGetSymbolAddress((void**)&featT, g_featT);
    cudaGetSymbolAddress((void**)&xb,    g_x);
    cudaGetSymbolAddress((void**)&w1t,   g_W1T);
    cudaGetSymbolAddress((void**)&w2t,   g_W2T);
    cudaGetSymbolAddress((void**)&wht,   g_WhT);
    cudaGetSymbolAddress((void**)&bh,    g_bh);
    cudaGetSymbolAddress((void**)&h1,    g_h1);
    cudaGetSymbolAddress((void**)&h2,    g_h2);
    cudaGetSymbolAddress((void**)&head,  g_head);
    cudaGetSymbolAddress((void**)&locp4, g_locp4);
    cudaGetSymbolAddress((void**)&partb, g_part);

    static cudaStream_t s2 = nullptr;
    static cudaEvent_t evFork = nullptr, evJoin = nullptr, evFork2 = nullptr, evJoin2 = nullptr;
    if (!s2) {
        cudaStreamCreateWithFlags(&s2, cudaStreamNonBlocking);
        cudaEventCreateWithFlags(&evFork,  cudaEventDisableTiming);
        cudaEventCreateWithFlags(&evJoin,  cudaEventDisableTiming);
        cudaEventCreateWithFlags(&evFork2, cudaEventDisableTiming);
        cudaEventCreateWithFlags(&evJoin2, cudaEventDisableTiming);
    }

    // ---- fork: weights on s2, features+pool on default ----
    cudaEventRecord(evFork, 0);
    cudaStreamWaitEvent(s2, evFork, 0);

    prep_w<<<3744, 256, 0, s2>>>(W1, W2, Wcls, Wloc, bcls, bloc, w1t, w2t, wht, bh);
    cudaEventRecord(evJoin, s2);

    prep_feat<<<2125, 256>>>(P2, P3, P4, P5, featT);
    pool_v3<<<NROI, 512>>>(rois, (const __half2*)featT, (__half2*)xb);

    cudaStreamWaitEvent(0, evJoin, 0);

    // FC1 (split-K = 8 -> 512 CTAs, ~3.4 CTAs/SM)
    gemm_hmma<<<dim3(HID / 64, NROI / 128, 8), 256>>>(xb, w1t, partb, HID, KDIM, KDIM / 8);
    combine_kernel<8, true, true><<<(NROI * HID / 4 + 255) / 256, 256>>>(partb, b1, h1, HID);

    // FC2 (split-K = 4)
    gemm_hmma<<<dim3(HID / 64, NROI / 128, 4), 256>>>(h1, w2t, partb, HID, HID, HID / 4);
    combine_kernel<4, true, true><<<(NROI * HID / 4 + 255) / 256, 256>>>(partb, b2, h2, HID);

    // ---- fork: loc_select on s2 parallel with head GEMM ----
    cudaEventRecord(evFork2, 0);
    cudaStreamWaitEvent(s2, evFork2, 0);
    loc_select_kernel<<<NROI, 128, 0, s2>>>(h2, wht, bh, label, locp4);
    cudaEventRecord(evJoin2, s2);

    gemm_direct<<<dim3(NCLSP / 64, NROI / 128), 256>>>(h2, wht, bh, head, NCLSP, HID);

    cudaStreamWaitEvent(0, evJoin2, 0);
    loss_kernel<<<1, 512>>>(head, locp4, label, loc, out);
}

// round 15
// speedup vs baseline: 1.0093x; 1.0093x over previous
#include <cuda_runtime.h>
#include <cuda_fp16.h>
#include <math.h>
#include <stdint.h>

#define NROI 512
#define NPOS 128
#define NCLS 81
#define KDIM 12544
#define HID  1024
#define NCLSP 128
#define NWROWS 512

// ---------------- scratch ----------------
__device__ __align__(256) __half g_featT[17408000];
__device__ __align__(256) __half g_x[NROI * KDIM];
__device__ __align__(256) __half g_W1T[HID * KDIM];
__device__ __align__(256) __half g_W2T[HID * HID];
__device__ __align__(256) __half g_WhT[NWROWS * HID];
__device__ float g_bh[NWROWS];
__device__ __align__(256) __half g_h1[NROI * HID];
__device__ __align__(256) __half g_h2[NROI * HID];
__device__ float g_head[NROI * NCLSP];
__device__ float g_locp4[NROI * 4];
__device__ float g_part[8 * NROI * HID];

// ---------------- helpers ----------------
__device__ __forceinline__ uint32_t smem_u32(const void* p) {
    uint32_t a;
    asm("{ .reg .u64 t; cvta.to.shared.u64 t, %1; cvt.u32.u64 %0, t; }" : "=r"(a) : "l"(p));
    return a;
}
#define CP_ASYNC16(dst, src) asm volatile("cp.async.cg.shared.global [%0], [%1], 16;" :: "r"(dst), "l"(src))
#define CP_COMMIT() asm volatile("cp.async.commit_group;" ::: "memory")
#define CP_WAIT(n)  asm volatile("cp.async.wait_group %0;" :: "n"(n) : "memory")

#define LDSM_X4(r0, r1, r2, r3, a) \
    asm volatile("ldmatrix.sync.aligned.m8n8.x4.shared.b16 {%0,%1,%2,%3}, [%4];" \
        : "=r"(r0), "=r"(r1), "=r"(r2), "=r"(r3) : "r"(a))

#define MMA16816(d, a, b0, b1) \
    asm volatile("mma.sync.aligned.m16n8k16.row.col.f32.f16.f16.f32 " \
        "{%0,%1,%2,%3}, {%4,%5,%6,%7}, {%8,%9}, {%0,%1,%2,%3};" \
        : "+f"((d)[0]), "+f"((d)[1]), "+f"((d)[2]), "+f"((d)[3]) \
        : "r"((a)[0]), "r"((a)[1]), "r"((a)[2]), "r"((a)[3]), "r"(b0), "r"(b1))

// ============ feature transpose: 2125 blocks ============
__global__ void __launch_bounds__(256) prep_feat(
        const float* __restrict__ P2, const float* __restrict__ P3,
        const float* __restrict__ P4, const float* __restrict__ P5,
        __half* __restrict__ featT) {
    __shared__ __align__(16) __half2 s2[32][132];
    int b = blockIdx.x;
    int w = threadIdx.x >> 5, l = threadIdx.x & 31;
    int lv, pt;
    if (b < 1600)      { lv = 0; pt = b; }
    else if (b < 2000) { lv = 1; pt = b - 1600; }
    else if (b < 2100) { lv = 2; pt = b - 2000; }
    else               { lv = 3; pt = b - 2100; }
    const int HWs[4]   = {51200, 12800, 3200, 800};
    const int bases[4] = {0, 13107200, 16384000, 17203200};
    const float* srcs[4] = {P2, P3, P4, P5};
    int HW = HWs[lv];
    const float* src = srcs[lv];
    __half* dst = featT + bases[lv];
    int p0 = pt * 32;
    #pragma unroll
    for (int m = 0; m < 4; m++) {
        int cp0 = w * 16 + m * 4;
        __half2 v[4];
        #pragma unroll
        for (int q = 0; q < 4; q++) {
            int c = 2 * (cp0 + q);
            float a = src[(size_t)c * HW + p0 + l];
            float bb = src[(size_t)(c + 1) * HW + p0 + l];
            v[q] = __floats2half2_rn(a, bb);
        }
        *(uint4*)&s2[l][cp0] = *(uint4*)v;
    }
    __syncthreads();
    #pragma unroll
    for (int j = 0; j < 4; j++) {
        int idx = j * 256 + threadIdx.x;
        int pos = idx >> 5, seg = idx & 31;
        uint4 val = *(uint4*)&s2[pos][seg * 4];
        *(uint4*)(dst + (size_t)(p0 + pos) * 256 + seg * 8) = val;
    }
}

// ============ weight prep: 3744 blocks ============
__global__ void __launch_bounds__(256) prep_w(
        const float* __restrict__ W1, const float* __restrict__ W2,
        const float* __restrict__ Wcls, const float* __restrict__ Wloc,
        const float* __restrict__ bcls, const float* __restrict__ bloc,
        __half* __restrict__ W1T, __half* __restrict__ W2T,
        __half* __restrict__ WhT, float* __restrict__ bh) {
    __shared__ __align__(16) __half2 s2[32][132];
    int b = blockIdx.x;
    int w = threadIdx.x >> 5, l = threadIdx.x & 31;

    if (b < 1568) {
        int k0 = (b % 49) * 256;
        int j0 = (b / 49) * 32;
        #pragma unroll
        for (int m = 0; m < 4; m++) {
            int cp0 = w * 16 + m * 4;
            __half2 v[4];
            #pragma unroll
            for (int q = 0; q < 4; q++) {
                int ka = k0 + 2 * (cp0 + q), kb = ka + 1;
                int ra = (ka & 255) * 49 + (ka >> 8);
                int rb = (kb & 255) * 49 + (kb >> 8);
                float a = W1[(size_t)ra * HID + j0 + l];
                float bb = W1[(size_t)rb * HID + j0 + l];
                v[q] = __floats2half2_rn(a, bb);
            }
            *(uint4*)&s2[l][cp0] = *(uint4*)v;
        }
        __syncthreads();
        #pragma unroll
        for (int j = 0; j < 4; j++) {
            int idx = j * 256 + threadIdx.x;
            int jr = idx >> 5, seg = idx & 31;
            uint4 val = *(uint4*)&s2[jr][seg * 4];
            *(uint4*)(W1T + (size_t)(j0 + jr) * KDIM + k0 + seg * 8) = val;
        }
    } else if (b < 1696) {
        int lb = b - 1568;
        int k0 = (lb & 3) * 256;
        int j0 = (lb >> 2) * 32;
        #pragma unroll
        for (int m = 0; m < 4; m++) {
            int cp0 = w * 16 + m * 4;
            __half2 v[4];
            #pragma unroll
            for (int q = 0; q < 4; q++) {
                int ka = k0 + 2 * (cp0 + q);
                float a = W2[(size_t)ka * HID + j0 + l];
                float bb = W2[(size_t)(ka + 1) * HID + j0 + l];
                v[q] = __floats2half2_rn(a, bb);
            }
            *(uint4*)&s2[l][cp0] = *(uint4*)v;
        }
        __syncthreads();
        #pragma unroll
        for (int j = 0; j < 4; j++) {
            int idx = j * 256 + threadIdx.x;
            int jr = idx >> 5, seg = idx & 31;
            uint4 val = *(uint4*)&s2[jr][seg * 4];
            *(uint4*)(W2T + (size_t)(j0 + jr) * HID + k0 + seg * 8) = val;
        }
    } else {
        int lb = b - 1696;
        int j = lb >> 2;
        int k = (lb & 3) * 256 + threadIdx.x;
        float v = 0.0f;
        if (j < NCLSP) {
            if (j < NCLS) v = Wcls[(size_t)k * NCLS + j];
        } else {
            int jj = j - NCLSP;
            if (jj < NCLS * 4) v = Wloc[(size_t)k * (NCLS * 4) + jj];
        }
        WhT[(size_t)j * HID + k] = __float2half(v);
        if ((lb & 3) == 0 && threadIdx.x == 0) {
            float bv = 0.0f;
            if (j < NCLSP) { if (j < NCLS) bv = bcls[j]; }
            else { int jj = j - NCLSP; if (jj < NCLS * 4) bv = bloc[jj]; }
            bh[j] = bv;
        }
    }
}

// ============ RoIAlign: 512 threads ============
__global__ void __launch_bounds__(512) pool_v3(const float* __restrict__ rois,
                                               const __half2* __restrict__ featT2,
                                               __half2* __restrict__ xout2) {
    int n = blockIdx.x;
    int cidx = threadIdx.x & 127;
    int h = threadIdx.x >> 7;

    float rx1 = rois[n * 4 + 0], ry1 = rois[n * 4 + 1];
    float rx2 = rois[n * 4 + 2], ry2 = rois[n * 4 + 3];
    float area = (rx2 - rx1 + 1.0f) * (ry2 - ry1 + 1.0f);
    float lf = floorf(4.0f + log2f(sqrtf(area) / 224.0f));
    lf = fminf(fmaxf(lf, 2.0f), 5.0f);
    int lv = (int)lf - 2;

    const int   Hs[4]     = {200, 100, 50, 25};
    const int   Ws[4]     = {256, 128, 64, 32};
    const int   bases2[4] = {0, 6553600, 8192000, 8601600};
    const float scl[4]    = {0.25f, 0.125f, 0.0625f, 0.03125f};

    int H = Hs[lv], W = Ws[lv];
    const __half2* ft = featT2 + bases2[lv];
    float scale = scl[lv];

    float x1 = rx1 * scale, y1 = ry1 * scale;
    float x2 = rx2 * scale, y2 = ry2 * scale;
    float bw = fmaxf(x2 - x1, 1.0f) / 7.0f;
    float bh = fmaxf(y2 - y1, 1.0f) / 7.0f;

    for (int bin = h; bin < 49; bin += 4) {
        int oy = bin / 7, ox = bin % 7;
        float2 acc = make_float2(0.0f, 0.0f);
        #pragma unroll
        for (int sy = 0; sy < 2; sy++) {
            #pragma unroll
            for (int sx = 0; sx < 2; sx++) {
                float px = x1 + ((float)ox + ((float)sx + 0.5f) * 0.5f) * bw;
                float py = y1 + ((float)oy + ((float)sy + 0.5f) * 0.5f) * bh;
                bool valid = (px > -1.0f) && (px < (float)W) && (py > -1.0f) && (py < (float)H);
                if (!valid) continue;
                float xx = fminf(fmaxf(px, 0.0f), (float)(W - 1));
                float yy = fminf(fmaxf(py, 0.0f), (float)(H - 1));
                float x0f = floorf(xx), y0f = floorf(yy);
                float lx = xx - x0f, ly = yy - y0f;
                int x0 = (int)x0f, y0 = (int)y0f;
                int x1i = min(x0 + 1, W - 1), y1i = min(y0 + 1, H - 1);
                const __half2* r0 = ft + (size_t)(y0  * W) * 128;
                const __half2* r1 = ft + (size_t)(y1i * W) * 128;
                float w00 = (1.0f - ly) * (1.0f - lx);
                float w01 = (1.0f - ly) * lx;
                float w10 = ly * (1.0f - lx);
                float w11 = ly * lx;
                float2 v00 = __half22float2(r0[x0  * 128 + cidx]);
                float2 v01 = __half22float2(r0[x1i * 128 + cidx]);
                float2 v10 = __half22float2(r1[x0  * 128 + cidx]);
                float2 v11 = __half22float2(r1[x1i * 128 + cidx]);
                acc.x += w00 * v00.x + w01 * v01.x + w10 * v10.x + w11 * v11.x;
                acc.y += w00 * v00.y + w01 * v01.y + w10 * v10.y + w11 * v11.y;
            }
        }
        xout2[(size_t)n * (KDIM / 2) + bin * 128 + cidx] =
            __floats2half2_rn(acc.x * 0.25f, acc.y * 0.25f);
    }
}

// ---------------- HMMA GEMM, 4-stage pipeline, split-K partials ----------------
__global__ void __launch_bounds__(256) gemm_hmma(const __half* __restrict__ A,
                                                 const __half* __restrict__ Bt,
                                                 float* __restrict__ part,
                                                 int N, int Krow, int ksplit) {
    __shared__ __align__(128) __half As[4][128 * 32];
    __shared__ __align__(128) __half Bs[4][64 * 32];

    int tid = threadIdx.x, wid = tid >> 5, lane = tid & 31;
    int m0 = blockIdx.y * 128, n0 = blockIdx.x * 64;
    int z = blockIdx.z;
    int kb0 = z * ksplit;
    int wm = (wid & 3) * 32;
    int wn = (wid >> 2) * 32;

    uint32_t sA = smem_u32(As), sB = smem_u32(Bs);
    int nch = ksplit >> 5;

    int ldr = tid >> 2, ldc = tid & 3;
    int sw0 = (ldc ^ ((ldr >> 1) & 3));
    int row1 = ldr + 64;
    int sw1 = (ldc ^ ((row1 >> 1) & 3));
    uint32_t stA0 = sA + (ldr * 32 + sw0 * 8) * 2;
    uint32_t stA1 = sA + (row1 * 32 + sw1 * 8) * 2;
    uint32_t stB0 = sB + (ldr * 32 + sw0 * 8) * 2;
    const char* gA0 = (const char*)(A + (size_t)(m0 + ldr) * Krow + kb0) + ldc * 16;
    const char* gA1 = (const char*)(A + (size_t)(m0 + row1) * Krow + kb0) + ldc * 16;
    const char* gB0 = (const char*)(Bt + (size_t)(n0 + ldr) * Krow + kb0) + ldc * 16;

    #pragma unroll
    for (int p = 0; p < 3; p++) {
        int koff = p << 6;
        CP_ASYNC16(stA0 + p * 8192, gA0 + koff);
        CP_ASYNC16(stA1 + p * 8192, gA1 + koff);
        CP_ASYNC16(stB0 + p * 4096, gB0 + koff);
        CP_COMMIT();
    }

    float acc[2][4][4];
    #pragma unroll
    for (int mi = 0; mi < 2; mi++)
        #pragma unroll
        for (int ni = 0; ni < 4; ni++)
            #pragma unroll
            for (int j = 0; j < 4; j++) acc[mi][ni][j] = 0.0f;

    for (int k = 0; k < nch; k++) {
        if (k + 3 < nch) { CP_WAIT(2); } else { CP_WAIT(0); }
        __syncthreads();
        if (k + 3 < nch) {
            int p = (k + 3) & 3;
            int koff = (k + 3) << 6;
            CP_ASYNC16(stA0 + p * 8192, gA0 + koff);
            CP_ASYNC16(stA1 + p * 8192, gA1 + koff);
            CP_ASYNC16(stB0 + p * 4096, gB0 + koff);
            CP_COMMIT();
        }
        int buf = k & 3;

        uint32_t bf[4][4];
        #pragma unroll
        for (int ni = 0; ni < 4; ni++) {
            int row = wn + ni * 8 + (lane & 7);
            int ch = lane >> 3;
            int sw = ch ^ ((row >> 1) & 3);
            uint32_t a = sB + (buf * 2048 + row * 32 + sw * 8) * 2;
            LDSM_X4(bf[ni][0], bf[ni][1], bf[ni][2], bf[ni][3], a);
        }
        #pragma unroll
        for (int s = 0; s < 2; s++) {
            uint32_t af[2][4];
            #pragma unroll
            for (int mi = 0; mi < 2; mi++) {
                int row = wm + mi * 16 + (lane & 15);
                int ch = 2 * s + (lane >> 4);
                int sw = ch ^ ((row >> 1) & 3);
                uint32_t a = sA + (buf * 4096 + row * 32 + sw * 8) * 2;
                LDSM_X4(af[mi][0], af[mi][1], af[mi][2], af[mi][3], a);
            }
            #pragma unroll
            for (int mi = 0; mi < 2; mi++)
                #pragma unroll
                for (int ni = 0; ni < 4; ni++)
                    MMA16816(acc[mi][ni], af[mi], bf[ni][2 * s], bf[ni][2 * s + 1]);
        }
    }

    float* out = part + (size_t)z * NROI * N;
    #pragma unroll
    for (int mi = 0; mi < 2; mi++) {
        #pragma unroll
        for (int ni = 0; ni < 4; ni++) {
            int m = m0 + wm + mi * 16 + (lane >> 2);
            int n = n0 + wn + ni * 8 + (lane & 3) * 2;
            out[(size_t)m * N + n]           = acc[mi][ni][0];
            out[(size_t)m * N + n + 1]       = acc[mi][ni][1];
            out[(size_t)(m + 8) * N + n]     = acc[mi][ni][2];
            out[(size_t)(m + 8) * N + n + 1] = acc[mi][ni][3];
        }
    }
}

// ---------------- direct GEMM: no split, fused bias (+ReLU, half/float out) ----------------
template <bool RELU, bool HOUT>
__global__ void __launch_bounds__(256) gemm_direct(const __half* __restrict__ A,
                                                   const __half* __restrict__ Bt,
                                                   const float* __restrict__ bias,
                                                   void* __restrict__ Cout,
                                                   int N, int Krow) {
    __shared__ __align__(128) __half As[4][128 * 32];
    __shared__ __align__(128) __half Bs[4][64 * 32];

    int tid = threadIdx.x, wid = tid >> 5, lane = tid & 31;
    int m0 = blockIdx.y * 128, n0 = blockIdx.x * 64;
    int wm = (wid & 3) * 32;
    int wn = (wid >> 2) * 32;

    uint32_t sA = smem_u32(As), sB = smem_u32(Bs);
    int nch = Krow >> 5;

    int ldr = tid >> 2, ldc = tid & 3;
    int sw0 = (ldc ^ ((ldr >> 1) & 3));
    int row1 = ldr + 64;
    int sw1 = (ldc ^ ((row1 >> 1) & 3));
    uint32_t stA0 = sA + (ldr * 32 + sw0 * 8) * 2;
    uint32_t stA1 = sA + (row1 * 32 + sw1 * 8) * 2;
    uint32_t stB0 = sB + (ldr * 32 + sw0 * 8) * 2;
    const char* gA0 = (const char*)(A + (size_t)(m0 + ldr) * Krow) + ldc * 16;
    const char* gA1 = (const char*)(A + (size_t)(m0 + row1) * Krow) + ldc * 16;
    const char* gB0 = (const char*)(Bt + (size_t)(n0 + ldr) * Krow) + ldc * 16;

    #pragma unroll
    for (int p = 0; p < 3; p++) {
        int koff = p << 6;
        CP_ASYNC16(stA0 + p * 8192, gA0 + koff);
        CP_ASYNC16(stA1 + p * 8192, gA1 + koff);
        CP_ASYNC16(stB0 + p * 4096, gB0 + koff);
        CP_COMMIT();
    }

    float acc[2][4][4];
    #pragma unroll
    for (int mi = 0; mi < 2; mi++)
        #pragma unroll
        for (int ni = 0; ni < 4; ni++)
            #pragma unroll
            for (int j = 0; j < 4; j++) acc[mi][ni][j] = 0.0f;

    for (int k = 0; k < nch; k++) {
        if (k + 3 < nch) { CP_WAIT(2); } else { CP_WAIT(0); }
        __syncthreads();
        if (k + 3 < nch) {
            int p = (k + 3) & 3;
            int koff = (k + 3) << 6;
            CP_ASYNC16(stA0 + p * 8192, gA0 + koff);
            CP_ASYNC16(stA1 + p * 8192, gA1 + koff);
            CP_ASYNC16(stB0 + p * 4096, gB0 + koff);
            CP_COMMIT();
        }
        int buf = k & 3;

        uint32_t bf[4][4];
        #pragma unroll
        for (int ni = 0; ni < 4; ni++) {
            int row = wn + ni * 8 + (lane & 7);
            int ch = lane >> 3;
            int sw = ch ^ ((row >> 1) & 3);
            uint32_t a = sB + (buf * 2048 + row * 32 + sw * 8) * 2;
            LDSM_X4(bf[ni][0], bf[ni][1], bf[ni][2], bf[ni][3], a);
        }
        #pragma unroll
        for (int s = 0; s < 2; s++) {
            uint32_t af[2][4];
            #pragma unroll
            for (int mi = 0; mi < 2; mi++) {
                int row = wm + mi * 16 + (lane & 15);
                int ch = 2 * s + (lane >> 4);
                int sw = ch ^ ((row >> 1) & 3);
                uint32_t a = sA + (buf * 4096 + row * 32 + sw * 8) * 2;
                LDSM_X4(af[mi][0], af[mi][1], af[mi][2], af[mi][3], a);
            }
            #pragma unroll
            for (int mi = 0; mi < 2; mi++)
                #pragma unroll
                for (int ni = 0; ni < 4; ni++)
                    MMA16816(acc[mi][ni], af[mi], bf[ni][2 * s], bf[ni][2 * s + 1]);
        }
    }

    #pragma unroll
    for (int mi = 0; mi < 2; mi++) {
        #pragma unroll
        for (int ni = 0; ni < 4; ni++) {
            int m = m0 + wm + mi * 16 + (lane >> 2);
            int n = n0 + wn + ni * 8 + (lane & 3) * 2;
            float v0 = acc[mi][ni][0] + bias[n];
            float v1 = acc[mi][ni][1] + bias[n + 1];
            float v2 = acc[mi][ni][2] + bias[n];
            float v3 = acc[mi][ni][3] + bias[n + 1];
            if (RELU) {
                v0 = fmaxf(v0, 0.0f); v1 = fmaxf(v1, 0.0f);
                v2 = fmaxf(v2, 0.0f); v3 = fmaxf(v3, 0.0f);
            }
            if (HOUT) {
                __half* C = (__half*)Cout;
                C[(size_t)m * N + n]           = __float2half(v0);
                C[(size_t)m * N + n + 1]       = __float2half(v1);
                C[(size_t)(m + 8) * N + n]     = __float2half(v2);
                C[(size_t)(m + 8) * N + n + 1] = __float2half(v3);
            } else {
                float* C = (float*)Cout;
                C[(size_t)m * N + n]           = v0;
                C[(size_t)m * N + n + 1]       = v1;
                C[(size_t)(m + 8) * N + n]     = v2;
                C[(size_t)(m + 8) * N + n + 1] = v3;
            }
        }
    }
}

// ---------------- combine ----------------
template <int SPLIT, bool RELU, bool HOUT>
__global__ void combine_kernel(const float* __restrict__ part, const float* __restrict__ bias,
                               void* __restrict__ out, int N) {
    int q = blockIdx.x * 256 + threadIdx.x;
    int MN4 = NROI * N / 4;
    if (q >= MN4) return;
    int n = (q * 4) % N;
    float4 v = *(const float4*)(bias + n);
    #pragma unroll
    for (int z = 0; z < SPLIT; z++) {
        float4 p = *(const float4*)(part + (size_t)z * NROI * N + (size_t)q * 4);
        v.x += p.x; v.y += p.y; v.z += p.z; v.w += p.w;
    }
    if (RELU) {
        v.x = fmaxf(v.x, 0.0f); v.y = fmaxf(v.y, 0.0f);
        v.z = fmaxf(v.z, 0.0f); v.w = fmaxf(v.w, 0.0f);
    }
    if (HOUT) {
        __half2 h0 = __floats2half2_rn(v.x, v.y);
        __half2 h1 = __floats2half2_rn(v.z, v.w);
        ((uint2*)out)[q] = make_uint2(*(uint32_t*)&h0, *(uint32_t*)&h1);
    } else {
        ((float4*)out)[q] = v;
    }
}

// ---------------- loc select ----------------
__global__ void __launch_bounds__(128) loc_select_kernel(const __half* __restrict__ h2,
                                                         const __half* __restrict__ WhT,
                                                         const float* __restrict__ bh,
                                                         const int* __restrict__ label,
                                                         float* __restrict__ locp4) {
    int n = blockIdx.x;
    int j = threadIdx.x >> 5, lane = threadIdx.x & 31;
    int row = NCLSP + label[n] * 4 + j;
    const __half2* hv = (const __half2*)(h2 + (size_t)n * HID);
    const __half2* wv = (const __half2*)(WhT + (size_t)row * HID);
    float acc = 0.0f;
    #pragma unroll
    for (int i = 0; i < 16; i++) {
        float2 a = __half22float2(hv[lane + i * 32]);
        float2 b = __half22float2(wv[lane + i * 32]);
        acc += a.x * b.x + a.y * b.y;
    }
    #pragma unroll
    for (int off = 16; off > 0; off >>= 1)
        acc += __shfl_down_sync(0xFFFFFFFF, acc, off);
    if (lane == 0) locp4[n * 4 + j] = acc + bh[row];
}

// ---------------- loss ----------------
__global__ void loss_kernel(const float* __restrict__ head, const float* __restrict__ locp4,
                            const int* __restrict__ label, const float* __restrict__ loc,
                            float* __restrict__ out) {
    __shared__ float red[512];
    int n = threadIdx.x;
    const float* lg = head + (size_t)n * NCLSP;

    float mx = -1e30f;
    for (int j = 0; j < NCLS; j++) mx = fmaxf(mx, lg[j]);
    float s = 0.0f;
    for (int j = 0; j < NCLS; j++) s += expf(lg[j] - mx);
    int lab = label[n];
    float logp = lg[lab] - mx - logf(s);
    float contrib = -logp * (1.0f / (float)NROI);

    if (n < NPOS) {
        #pragma unroll
        for (int j = 0; j < 4; j++) {
            float d = fabsf(locp4[n * 4 + j] - loc[n * 4 + j]);
            float sl1 = (d < 1.0f) ? 0.5f * d * d : d - 0.5f;
            contrib += sl1 * (1.0f / (float)NROI);
        }
    }
    red[n] = contrib;
    __syncthreads();
    for (int stride = 256; stride > 0; stride >>= 1) {
        if (n < stride) red[n] += red[n + stride];
        __syncthreads();
    }
    if (n == 0) out[0] = red[0];
}

// ---------------- launch (two-stream fork/join) ----------------
extern "C" void kernel_launch(void* const* d_in, const int* in_sizes, int n_in,
                              void* d_out, int out_size) {
    const float* P2    = (const float*)d_in[0];
    const float* P3    = (const float*)d_in[1];
    const float* P4    = (const float*)d_in[2];
    const float* P5    = (const float*)d_in[3];
    const float* rois  = (const float*)d_in[4];
    const int*   label = (const int*)  d_in[5];
    const float* loc   = (const float*)d_in[6];
    const float* W1    = (const float*)d_in[7];
    const float* b1    = (const float*)d_in[8];
    const float* W2    = (const float*)d_in[9];
    const float* b2    = (const float*)d_in[10];
    const float* Wcls  = (const float*)d_in[11];
    const float* bcls  = (const float*)d_in[12];
    const float* Wloc  = (const float*)d_in[13];
    const float* bloc  = (const float*)d_in[14];
    float* out = (float*)d_out;

    __half *featT, *xb, *w1t, *w2t, *wht, *h1, *h2;
    float *bh, *head, *locp4, *partb;
    cudaGetSymbolAddress((void**)&featT, g_featT);
    cudaGetSymbolAddress((void**)&xb,    g_x);
    cudaGetSymbolAddress((void**)&w1t,   g_W1T);
    cudaGetSymbolAddress((void**)&w2t,   g_W2T);
    cudaGetSymbolAddress((void**)&wht,   g_WhT);
    cudaGetSymbolAddress((void**)&bh,    g_bh);
    cudaGetSymbolAddress((void**)&h1,    g_h1);
    cudaGetSymbolAddress((void**)&h2,    g_h2);
    cudaGetSymbolAddress((void**)&head,  g_head);
    cudaGetSymbolAddress((void**)&locp4, g_locp4);
    cudaGetSymbolAddress((void**)&partb, g_part);

    static cudaStream_t s2 = nullptr;
    static cudaEvent_t evFork = nullptr, evJoin = nullptr, evFork2 = nullptr, evJoin2 = nullptr;
    if (!s2) {
        cudaStreamCreateWithFlags(&s2, cudaStreamNonBlocking);
        cudaEventCreateWithFlags(&evFork,  cudaEventDisableTiming);
        cudaEventCreateWithFlags(&evJoin,  cudaEventDisableTiming);
        cudaEventCreateWithFlags(&evFork2, cudaEventDisableTiming);
        cudaEventCreateWithFlags(&evJoin2, cudaEventDisableTiming);
    }

    // ---- fork: weights on s2, features+pool on default ----
    cudaEventRecord(evFork, 0);
    cudaStreamWaitEvent(s2, evFork, 0);

    prep_w<<<3744, 256, 0, s2>>>(W1, W2, Wcls, Wloc, bcls, bloc, w1t, w2t, wht, bh);
    cudaEventRecord(evJoin, s2);

    prep_feat<<<2125, 256>>>(P2, P3, P4, P5, featT);
    pool_v3<<<NROI, 512>>>(rois, (const __half2*)featT, (__half2*)xb);

    cudaStreamWaitEvent(0, evJoin, 0);

    // FC1 (split-K = 4, proven best)
    gemm_hmma<<<dim3(HID / 64, NROI / 128, 4), 256>>>(xb, w1t, partb, HID, KDIM, KDIM / 4);
    combine_kernel<4, true, true><<<(NROI * HID / 4 + 255) / 256, 256>>>(partb, b1, h1, HID);

    // FC2: single pass, fused bias+ReLU+fp16 epilogue (no combine launch)
    gemm_direct<true, true><<<dim3(HID / 64, NROI / 128), 256>>>(h1, w2t, b2, h2, HID, HID);

    // ---- fork: loc_select on s2 parallel with head GEMM ----
    cudaEventRecord(evFork2, 0);
    cudaStreamWaitEvent(s2, evFork2, 0);
    loc_select_kernel<<<NROI, 128, 0, s2>>>(h2, wht, bh, label, locp4);
    cudaEventRecord(evJoin2, s2);

    gemm_direct<false, false><<<dim3(NCLSP / 64, NROI / 128), 256>>>(h2, wht, bh, head, NCLSP, HID);

    cudaStreamWaitEvent(0, evJoin2, 0);
    loss_kernel<<<1, 512>>>(head, locp4, label, loc, out);
}

// round 16
// speedup vs baseline: 1.0302x; 1.0206x over previous
#include <cuda_runtime.h>
#include <cuda_fp16.h>
#include <math.h>
#include <stdint.h>

#define NROI 512
#define NPOS 128
#define NCLS 81
#define KDIM 12544
#define HID  1024
#define NCLSP 128
#define NWROWS 512

// ---------------- scratch ----------------
__device__ __align__(256) __half g_featT[17408000];
__device__ __align__(256) __half g_x[NROI * KDIM];
__device__ __align__(256) __half g_W1T[HID * KDIM];
__device__ __align__(256) __half g_W2T[HID * HID];
__device__ __align__(256) __half g_WhT[NWROWS * HID];
__device__ float g_bh[NWROWS];
__device__ __align__(256) __half g_h1[NROI * HID];
__device__ __align__(256) __half g_h2[NROI * HID];
__device__ float g_head[NROI * NCLSP];
__device__ float g_locp4[NROI * 4];
__device__ float g_part[8 * NROI * HID];

// ---------------- helpers ----------------
__device__ __forceinline__ uint32_t smem_u32(const void* p) {
    uint32_t a;
    asm("{ .reg .u64 t; cvta.to.shared.u64 t, %1; cvt.u32.u64 %0, t; }" : "=r"(a) : "l"(p));
    return a;
}
#define CP_ASYNC16(dst, src) asm volatile("cp.async.cg.shared.global [%0], [%1], 16;" :: "r"(dst), "l"(src))
#define CP_COMMIT() asm volatile("cp.async.commit_group;" ::: "memory")
#define CP_WAIT(n)  asm volatile("cp.async.wait_group %0;" :: "n"(n) : "memory")

#define LDSM_X4(r0, r1, r2, r3, a) \
    asm volatile("ldmatrix.sync.aligned.m8n8.x4.shared.b16 {%0,%1,%2,%3}, [%4];" \
        : "=r"(r0), "=r"(r1), "=r"(r2), "=r"(r3) : "r"(a))

#define MMA16816(d, a, b0, b1) \
    asm volatile("mma.sync.aligned.m16n8k16.row.col.f32.f16.f16.f32 " \
        "{%0,%1,%2,%3}, {%4,%5,%6,%7}, {%8,%9}, {%0,%1,%2,%3};" \
        : "+f"((d)[0]), "+f"((d)[1]), "+f"((d)[2]), "+f"((d)[3]) \
        : "r"((a)[0]), "r"((a)[1]), "r"((a)[2]), "r"((a)[3]), "r"(b0), "r"(b1))

// ============ feature transpose: 2125 blocks ============
__global__ void __launch_bounds__(256) prep_feat(
        const float* __restrict__ P2, const float* __restrict__ P3,
        const float* __restrict__ P4, const float* __restrict__ P5,
        __half* __restrict__ featT) {
    __shared__ __align__(16) __half2 s2[32][132];
    int b = blockIdx.x;
    int w = threadIdx.x >> 5, l = threadIdx.x & 31;
    int lv, pt;
    if (b < 1600)      { lv = 0; pt = b; }
    else if (b < 2000) { lv = 1; pt = b - 1600; }
    else if (b < 2100) { lv = 2; pt = b - 2000; }
    else               { lv = 3; pt = b - 2100; }
    const int HWs[4]   = {51200, 12800, 3200, 800};
    const int bases[4] = {0, 13107200, 16384000, 17203200};
    const float* srcs[4] = {P2, P3, P4, P5};
    int HW = HWs[lv];
    const float* src = srcs[lv];
    __half* dst = featT + bases[lv];
    int p0 = pt * 32;
    #pragma unroll
    for (int m = 0; m < 4; m++) {
        int cp0 = w * 16 + m * 4;
        __half2 v[4];
        #pragma unroll
        for (int q = 0; q < 4; q++) {
            int c = 2 * (cp0 + q);
            float a = src[(size_t)c * HW + p0 + l];
            float bb = src[(size_t)(c + 1) * HW + p0 + l];
            v[q] = __floats2half2_rn(a, bb);
        }
        *(uint4*)&s2[l][cp0] = *(uint4*)v;
    }
    __syncthreads();
    #pragma unroll
    for (int j = 0; j < 4; j++) {
        int idx = j * 256 + threadIdx.x;
        int pos = idx >> 5, seg = idx & 31;
        uint4 val = *(uint4*)&s2[pos][seg * 4];
        *(uint4*)(dst + (size_t)(p0 + pos) * 256 + seg * 8) = val;
    }
}

// ============ weight prep: 3744 blocks ============
__global__ void __launch_bounds__(256) prep_w(
        const float* __restrict__ W1, const float* __restrict__ W2,
        const float* __restrict__ Wcls, const float* __restrict__ Wloc,
        const float* __restrict__ bcls, const float* __restrict__ bloc,
        __half* __restrict__ W1T, __half* __restrict__ W2T,
        __half* __restrict__ WhT, float* __restrict__ bh) {
    __shared__ __align__(16) __half2 s2[32][132];
    int b = blockIdx.x;
    int w = threadIdx.x >> 5, l = threadIdx.x & 31;

    if (b < 1568) {
        int k0 = (b % 49) * 256;
        int j0 = (b / 49) * 32;
        #pragma unroll
        for (int m = 0; m < 4; m++) {
            int cp0 = w * 16 + m * 4;
            __half2 v[4];
            #pragma unroll
            for (int q = 0; q < 4; q++) {
                int ka = k0 + 2 * (cp0 + q), kb = ka + 1;
                int ra = (ka & 255) * 49 + (ka >> 8);
                int rb = (kb & 255) * 49 + (kb >> 8);
                float a = W1[(size_t)ra * HID + j0 + l];
                float bb = W1[(size_t)rb * HID + j0 + l];
                v[q] = __floats2half2_rn(a, bb);
            }
            *(uint4*)&s2[l][cp0] = *(uint4*)v;
        }
        __syncthreads();
        #pragma unroll
        for (int j = 0; j < 4; j++) {
            int idx = j * 256 + threadIdx.x;
            int jr = idx >> 5, seg = idx & 31;
            uint4 val = *(uint4*)&s2[jr][seg * 4];
            *(uint4*)(W1T + (size_t)(j0 + jr) * KDIM + k0 + seg * 8) = val;
        }
    } else if (b < 1696) {
        int lb = b - 1568;
        int k0 = (lb & 3) * 256;
        int j0 = (lb >> 2) * 32;
        #pragma unroll
        for (int m = 0; m < 4; m++) {
            int cp0 = w * 16 + m * 4;
            __half2 v[4];
            #pragma unroll
            for (int q = 0; q < 4; q++) {
                int ka = k0 + 2 * (cp0 + q);
                float a = W2[(size_t)ka * HID + j0 + l];
                float bb = W2[(size_t)(ka + 1) * HID + j0 + l];
                v[q] = __floats2half2_rn(a, bb);
            }
            *(uint4*)&s2[l][cp0] = *(uint4*)v;
        }
        __syncthreads();
        #pragma unroll
        for (int j = 0; j < 4; j++) {
            int idx = j * 256 + threadIdx.x;
            int jr = idx >> 5, seg = idx & 31;
            uint4 val = *(uint4*)&s2[jr][seg * 4];
            *(uint4*)(W2T + (size_t)(j0 + jr) * HID + k0 + seg * 8) = val;
        }
    } else {
        int lb = b - 1696;
        int j = lb >> 2;
        int k = (lb & 3) * 256 + threadIdx.x;
        float v = 0.0f;
        if (j < NCLSP) {
            if (j < NCLS) v = Wcls[(size_t)k * NCLS + j];
        } else {
            int jj = j - NCLSP;
            if (jj < NCLS * 4) v = Wloc[(size_t)k * (NCLS * 4) + jj];
        }
        WhT[(size_t)j * HID + k] = __float2half(v);
        if ((lb & 3) == 0 && threadIdx.x == 0) {
            float bv = 0.0f;
            if (j < NCLSP) { if (j < NCLS) bv = bcls[j]; }
            else { int jj = j - NCLSP; if (jj < NCLS * 4) bv = bloc[jj]; }
            bh[j] = bv;
        }
    }
}

// ============ RoIAlign: 512 threads ============
__global__ void __launch_bounds__(512) pool_v3(const float* __restrict__ rois,
                                               const __half2* __restrict__ featT2,
                                               __half2* __restrict__ xout2) {
    int n = blockIdx.x;
    int cidx = threadIdx.x & 127;
    int h = threadIdx.x >> 7;

    float rx1 = rois[n * 4 + 0], ry1 = rois[n * 4 + 1];
    float rx2 = rois[n * 4 + 2], ry2 = rois[n * 4 + 3];
    float area = (rx2 - rx1 + 1.0f) * (ry2 - ry1 + 1.0f);
    float lf = floorf(4.0f + log2f(sqrtf(area) / 224.0f));
    lf = fminf(fmaxf(lf, 2.0f), 5.0f);
    int lv = (int)lf - 2;

    const int   Hs[4]     = {200, 100, 50, 25};
    const int   Ws[4]     = {256, 128, 64, 32};
    const int   bases2[4] = {0, 6553600, 8192000, 8601600};
    const float scl[4]    = {0.25f, 0.125f, 0.0625f, 0.03125f};

    int H = Hs[lv], W = Ws[lv];
    const __half2* ft = featT2 + bases2[lv];
    float scale = scl[lv];

    float x1 = rx1 * scale, y1 = ry1 * scale;
    float x2 = rx2 * scale, y2 = ry2 * scale;
    float bw = fmaxf(x2 - x1, 1.0f) / 7.0f;
    float bh = fmaxf(y2 - y1, 1.0f) / 7.0f;

    for (int bin = h; bin < 49; bin += 4) {
        int oy = bin / 7, ox = bin % 7;
        float2 acc = make_float2(0.0f, 0.0f);
        #pragma unroll
        for (int sy = 0; sy < 2; sy++) {
            #pragma unroll
            for (int sx = 0; sx < 2; sx++) {
                float px = x1 + ((float)ox + ((float)sx + 0.5f) * 0.5f) * bw;
                float py = y1 + ((float)oy + ((float)sy + 0.5f) * 0.5f) * bh;
                bool valid = (px > -1.0f) && (px < (float)W) && (py > -1.0f) && (py < (float)H);
                if (!valid) continue;
                float xx = fminf(fmaxf(px, 0.0f), (float)(W - 1));
                float yy = fminf(fmaxf(py, 0.0f), (float)(H - 1));
                float x0f = floorf(xx), y0f = floorf(yy);
                float lx = xx - x0f, ly = yy - y0f;
                int x0 = (int)x0f, y0 = (int)y0f;
                int x1i = min(x0 + 1, W - 1), y1i = min(y0 + 1, H - 1);
                const __half2* r0 = ft + (size_t)(y0  * W) * 128;
                const __half2* r1 = ft + (size_t)(y1i * W) * 128;
                float w00 = (1.0f - ly) * (1.0f - lx);
                float w01 = (1.0f - ly) * lx;
                float w10 = ly * (1.0f - lx);
                float w11 = ly * lx;
                float2 v00 = __half22float2(r0[x0  * 128 + cidx]);
                float2 v01 = __half22float2(r0[x1i * 128 + cidx]);
                float2 v10 = __half22float2(r1[x0  * 128 + cidx]);
                float2 v11 = __half22float2(r1[x1i * 128 + cidx]);
                acc.x += w00 * v00.x + w01 * v01.x + w10 * v10.x + w11 * v11.x;
                acc.y += w00 * v00.y + w01 * v01.y + w10 * v10.y + w11 * v11.y;
            }
        }
        xout2[(size_t)n * (KDIM / 2) + bin * 128 + cidx] =
            __floats2half2_rn(acc.x * 0.25f, acc.y * 0.25f);
    }
}

// ======== FC1 GEMM: BK=64, 3-stage dynamic smem, split-K partials ========
// rows of 64 halves (128B), swizzle: 16B-chunk ch ^= (row & 7).
__global__ void __launch_bounds__(256) gemm_hmma_w(const __half* __restrict__ A,
                                                   const __half* __restrict__ Bt,
                                                   float* __restrict__ part,
                                                   int N, int Krow, int ksplit) {
    extern __shared__ __align__(128) __half dsm[];
    __half* As = dsm;            // 3 stages x 8192 halves (16KB)
    __half* Bs = dsm + 24576;    // 3 stages x 4096 halves (8KB)

    int tid = threadIdx.x, wid = tid >> 5, lane = tid & 31;
    int m0 = blockIdx.y * 128, n0 = blockIdx.x * 64;
    int z = blockIdx.z;
    int kb0 = z * ksplit;
    int wm = (wid & 3) * 32;
    int wn = (wid >> 2) * 32;

    uint32_t sA = smem_u32(As), sB = smem_u32(Bs);
    int nch = ksplit >> 6;

    // store slots: A 4 per thread, B 2 per thread (16B each)
    uint32_t stA[4]; const char* gA[4];
    #pragma unroll
    for (int i = 0; i < 4; i++) {
        int idx = tid + i * 256;
        int row = idx >> 3, ch = idx & 7;
        int sw = ch ^ (row & 7);
        stA[i] = sA + (row * 64 + sw * 8) * 2;
        gA[i] = (const char*)(A + (size_t)(m0 + row) * Krow + kb0) + ch * 16;
    }
    uint32_t stB[2]; const char* gB[2];
    #pragma unroll
    for (int i = 0; i < 2; i++) {
        int idx = tid + i * 256;
        int row = idx >> 3, ch = idx & 7;
        int sw = ch ^ (row & 7);
        stB[i] = sB + (row * 64 + sw * 8) * 2;
        gB[i] = (const char*)(Bt + (size_t)(n0 + row) * Krow + kb0) + ch * 16;
    }

    // prologue: stages 0,1
    #pragma unroll
    for (int p = 0; p < 2; p++) {
        int koff = p * 128;   // 64 halves * 2B
        #pragma unroll
        for (int i = 0; i < 4; i++) CP_ASYNC16(stA[i] + p * 16384, gA[i] + koff);
        #pragma unroll
        for (int i = 0; i < 2; i++) CP_ASYNC16(stB[i] + p * 8192, gB[i] + koff);
        CP_COMMIT();
    }

    float acc[2][4][4];
    #pragma unroll
    for (int mi = 0; mi < 2; mi++)
        #pragma unroll
        for (int ni = 0; ni < 4; ni++)
            #pragma unroll
            for (int j = 0; j < 4; j++) acc[mi][ni][j] = 0.0f;

    for (int k = 0; k < nch; k++) {
        if (k + 2 < nch) { CP_WAIT(1); } else { CP_WAIT(0); }
        __syncthreads();
        if (k + 2 < nch) {
            int p = (k + 2) % 3;
            int koff = (k + 2) * 128;
            #pragma unroll
            for (int i = 0; i < 4; i++) CP_ASYNC16(stA[i] + p * 16384, gA[i] + koff);
            #pragma unroll
            for (int i = 0; i < 2; i++) CP_ASYNC16(stB[i] + p * 8192, gB[i] + koff);
            CP_COMMIT();
        }
        int buf = k % 3;

        #pragma unroll
        for (int s2 = 0; s2 < 2; s2++) {
            uint32_t bf[4][4];
            #pragma unroll
            for (int ni = 0; ni < 4; ni++) {
                int row = wn + ni * 8 + (lane & 7);
                int ch = s2 * 4 + (lane >> 3);
                int sw = ch ^ (row & 7);
                uint32_t a = sB + (buf * 4096 + row * 64 + sw * 8) * 2;
                LDSM_X4(bf[ni][0], bf[ni][1], bf[ni][2], bf[ni][3], a);
            }
            #pragma unroll
            for (int s = 0; s < 2; s++) {
                int sg = s2 * 2 + s;
                uint32_t af[2][4];
                #pragma unroll
                for (int mi = 0; mi < 2; mi++) {
                    int row = wm + mi * 16 + (lane & 15);
                    int ch = 2 * sg + (lane >> 4);
                    int sw = ch ^ (row & 7);
                    uint32_t a = sA + (buf * 8192 + row * 64 + sw * 8) * 2;
                    LDSM_X4(af[mi][0], af[mi][1], af[mi][2], af[mi][3], a);
                }
                #pragma unroll
                for (int mi = 0; mi < 2; mi++)
                    #pragma unroll
                    for (int ni = 0; ni < 4; ni++)
                        MMA16816(acc[mi][ni], af[mi], bf[ni][2 * s], bf[ni][2 * s + 1]);
            }
        }
    }

    float* out = part + (size_t)z * NROI * N;
    #pragma unroll
    for (int mi = 0; mi < 2; mi++) {
        #pragma unroll
        for (int ni = 0; ni < 4; ni++) {
            int m = m0 + wm + mi * 16 + (lane >> 2);
            int n = n0 + wn + ni * 8 + (lane & 3) * 2;
            out[(size_t)m * N + n]           = acc[mi][ni][0];
            out[(size_t)m * N + n + 1]       = acc[mi][ni][1];
            out[(size_t)(m + 8) * N + n]     = acc[mi][ni][2];
            out[(size_t)(m + 8) * N + n + 1] = acc[mi][ni][3];
        }
    }
}

// ---------------- FC2 GEMM (proven BK=32, 4-stage), split-K partials ----------------
__global__ void __launch_bounds__(256) gemm_hmma(const __half* __restrict__ A,
                                                 const __half* __restrict__ Bt,
                                                 float* __restrict__ part,
                                                 int N, int Krow, int ksplit) {
    __shared__ __align__(128) __half As[4][128 * 32];
    __shared__ __align__(128) __half Bs[4][64 * 32];

    int tid = threadIdx.x, wid = tid >> 5, lane = tid & 31;
    int m0 = blockIdx.y * 128, n0 = blockIdx.x * 64;
    int z = blockIdx.z;
    int kb0 = z * ksplit;
    int wm = (wid & 3) * 32;
    int wn = (wid >> 2) * 32;

    uint32_t sA = smem_u32(As), sB = smem_u32(Bs);
    int nch = ksplit >> 5;

    int ldr = tid >> 2, ldc = tid & 3;
    int sw0 = (ldc ^ ((ldr >> 1) & 3));
    int row1 = ldr + 64;
    int sw1 = (ldc ^ ((row1 >> 1) & 3));
    uint32_t stA0 = sA + (ldr * 32 + sw0 * 8) * 2;
    uint32_t stA1 = sA + (row1 * 32 + sw1 * 8) * 2;
    uint32_t stB0 = sB + (ldr * 32 + sw0 * 8) * 2;
    const char* gA0 = (const char*)(A + (size_t)(m0 + ldr) * Krow + kb0) + ldc * 16;
    const char* gA1 = (const char*)(A + (size_t)(m0 + row1) * Krow + kb0) + ldc * 16;
    const char* gB0 = (const char*)(Bt + (size_t)(n0 + ldr) * Krow + kb0) + ldc * 16;

    #pragma unroll
    for (int p = 0; p < 3; p++) {
        int koff = p << 6;
        CP_ASYNC16(stA0 + p * 8192, gA0 + koff);
        CP_ASYNC16(stA1 + p * 8192, gA1 + koff);
        CP_ASYNC16(stB0 + p * 4096, gB0 + koff);
        CP_COMMIT();
    }

    float acc[2][4][4];
    #pragma unroll
    for (int mi = 0; mi < 2; mi++)
        #pragma unroll
        for (int ni = 0; ni < 4; ni++)
            #pragma unroll
            for (int j = 0; j < 4; j++) acc[mi][ni][j] = 0.0f;

    for (int k = 0; k < nch; k++) {
        if (k + 3 < nch) { CP_WAIT(2); } else { CP_WAIT(0); }
        __syncthreads();
        if (k + 3 < nch) {
            int p = (k + 3) & 3;
            int koff = (k + 3) << 6;
            CP_ASYNC16(stA0 + p * 8192, gA0 + koff);
            CP_ASYNC16(stA1 + p * 8192, gA1 + koff);
            CP_ASYNC16(stB0 + p * 4096, gB0 + koff);
            CP_COMMIT();
        }
        int buf = k & 3;

        uint32_t bf[4][4];
        #pragma unroll
        for (int ni = 0; ni < 4; ni++) {
            int row = wn + ni * 8 + (lane & 7);
            int ch = lane >> 3;
            int sw = ch ^ ((row >> 1) & 3);
            uint32_t a = sB + (buf * 2048 + row * 32 + sw * 8) * 2;
            LDSM_X4(bf[ni][0], bf[ni][1], bf[ni][2], bf[ni][3], a);
        }
        #pragma unroll
        for (int s = 0; s < 2; s++) {
            uint32_t af[2][4];
            #pragma unroll
            for (int mi = 0; mi < 2; mi++) {
                int row = wm + mi * 16 + (lane & 15);
                int ch = 2 * s + (lane >> 4);
                int sw = ch ^ ((row >> 1) & 3);
                uint32_t a = sA + (buf * 4096 + row * 32 + sw * 8) * 2;
                LDSM_X4(af[mi][0], af[mi][1], af[mi][2], af[mi][3], a);
            }
            #pragma unroll
            for (int mi = 0; mi < 2; mi++)
                #pragma unroll
                for (int ni = 0; ni < 4; ni++)
                    MMA16816(acc[mi][ni], af[mi], bf[ni][2 * s], bf[ni][2 * s + 1]);
        }
    }

    float* out = part + (size_t)z * NROI * N;
    #pragma unroll
    for (int mi = 0; mi < 2; mi++) {
        #pragma unroll
        for (int ni = 0; ni < 4; ni++) {
            int m = m0 + wm + mi * 16 + (lane >> 2);
            int n = n0 + wn + ni * 8 + (lane & 3) * 2;
            out[(size_t)m * N + n]           = acc[mi][ni][0];
            out[(size_t)m * N + n + 1]       = acc[mi][ni][1];
            out[(size_t)(m + 8) * N + n]     = acc[mi][ni][2];
            out[(size_t)(m + 8) * N + n + 1] = acc[mi][ni][3];
        }
    }
}

// ---------------- head GEMM: no split, fused bias ----------------
__global__ void __launch_bounds__(256) gemm_direct(const __half* __restrict__ A,
                                                   const __half* __restrict__ Bt,
                                                   const float* __restrict__ bias,
                                                   float* __restrict__ Cout,
                                                   int N, int Krow) {
    __shared__ __align__(128) __half As[4][128 * 32];
    __shared__ __align__(128) __half Bs[4][64 * 32];

    int tid = threadIdx.x, wid = tid >> 5, lane = tid & 31;
    int m0 = blockIdx.y * 128, n0 = blockIdx.x * 64;
    int wm = (wid & 3) * 32;
    int wn = (wid >> 2) * 32;

    uint32_t sA = smem_u32(As), sB = smem_u32(Bs);
    int nch = Krow >> 5;

    int ldr = tid >> 2, ldc = tid & 3;
    int sw0 = (ldc ^ ((ldr >> 1) & 3));
    int row1 = ldr + 64;
    int sw1 = (ldc ^ ((row1 >> 1) & 3));
    uint32_t stA0 = sA + (ldr * 32 + sw0 * 8) * 2;
    uint32_t stA1 = sA + (row1 * 32 + sw1 * 8) * 2;
    uint32_t stB0 = sB + (ldr * 32 + sw0 * 8) * 2;
    const char* gA0 = (const char*)(A + (size_t)(m0 + ldr) * Krow) + ldc * 16;
    const char* gA1 = (const char*)(A + (size_t)(m0 + row1) * Krow) + ldc * 16;
    const char* gB0 = (const char*)(Bt + (size_t)(n0 + ldr) * Krow) + ldc * 16;

    #pragma unroll
    for (int p = 0; p < 3; p++) {
        int koff = p << 6;
        CP_ASYNC16(stA0 + p * 8192, gA0 + koff);
        CP_ASYNC16(stA1 + p * 8192, gA1 + koff);
        CP_ASYNC16(stB0 + p * 4096, gB0 + koff);
        CP_COMMIT();
    }

    float acc[2][4][4];
    #pragma unroll
    for (int mi = 0; mi < 2; mi++)
        #pragma unroll
        for (int ni = 0; ni < 4; ni++)
            #pragma unroll
            for (int j = 0; j < 4; j++) acc[mi][ni][j] = 0.0f;

    for (int k = 0; k < nch; k++) {
        if (k + 3 < nch) { CP_WAIT(2); } else { CP_WAIT(0); }
        __syncthreads();
        if (k + 3 < nch) {
            int p = (k + 3) & 3;
            int koff = (k + 3) << 6;
            CP_ASYNC16(stA0 + p * 8192, gA0 + koff);
            CP_ASYNC16(stA1 + p * 8192, gA1 + koff);
            CP_ASYNC16(stB0 + p * 4096, gB0 + koff);
            CP_COMMIT();
        }
        int buf = k & 3;

        uint32_t bf[4][4];
        #pragma unroll
        for (int ni = 0; ni < 4; ni++) {
            int row = wn + ni * 8 + (lane & 7);
            int ch = lane >> 3;
            int sw = ch ^ ((row >> 1) & 3);
            uint32_t a = sB + (buf * 2048 + row * 32 + sw * 8) * 2;
            LDSM_X4(bf[ni][0], bf[ni][1], bf[ni][2], bf[ni][3], a);
        }
        #pragma unroll
        for (int s = 0; s < 2; s++) {
            uint32_t af[2][4];
            #pragma unroll
            for (int mi = 0; mi < 2; mi++) {
                int row = wm + mi * 16 + (lane & 15);
                int ch = 2 * s + (lane >> 4);
                int sw = ch ^ ((row >> 1) & 3);
                uint32_t a = sA + (buf * 4096 + row * 32 + sw * 8) * 2;
                LDSM_X4(af[mi][0], af[mi][1], af[mi][2], af[mi][3], a);
            }
            #pragma unroll
            for (int mi = 0; mi < 2; mi++)
                #pragma unroll
                for (int ni = 0; ni < 4; ni++)
                    MMA16816(acc[mi][ni], af[mi], bf[ni][2 * s], bf[ni][2 * s + 1]);
        }
    }

    #pragma unroll
    for (int mi = 0; mi < 2; mi++) {
        #pragma unroll
        for (int ni = 0; ni < 4; ni++) {
            int m = m0 + wm + mi * 16 + (lane >> 2);
            int n = n0 + wn + ni * 8 + (lane & 3) * 2;
            Cout[(size_t)m * N + n]           = acc[mi][ni][0] + bias[n];
            Cout[(size_t)m * N + n + 1]       = acc[mi][ni][1] + bias[n + 1];
            Cout[(size_t)(m + 8) * N + n]     = acc[mi][ni][2] + bias[n];
            Cout[(size_t)(m + 8) * N + n + 1] = acc[mi][ni][3] + bias[n + 1];
        }
    }
}

// ---------------- combine ----------------
template <int SPLIT, bool RELU, bool HOUT>
__global__ void combine_kernel(const float* __restrict__ part, const float* __restrict__ bias,
                               void* __restrict__ out, int N) {
    int q = blockIdx.x * 256 + threadIdx.x;
    int MN4 = NROI * N / 4;
    if (q >= MN4) return;
    int n = (q * 4) % N;
    float4 v = *(const float4*)(bias + n);
    #pragma unroll
    for (int z = 0; z < SPLIT; z++) {
        float4 p = *(const float4*)(part + (size_t)z * NROI * N + (size_t)q * 4);
        v.x += p.x; v.y += p.y; v.z += p.z; v.w += p.w;
    }
    if (RELU) {
        v.x = fmaxf(v.x, 0.0f); v.y = fmaxf(v.y, 0.0f);
        v.z = fmaxf(v.z, 0.0f); v.w = fmaxf(v.w, 0.0f);
    }
    if (HOUT) {
        __half2 h0 = __floats2half2_rn(v.x, v.y);
        __half2 h1 = __floats2half2_rn(v.z, v.w);
        ((uint2*)out)[q] = make_uint2(*(uint32_t*)&h0, *(uint32_t*)&h1);
    } else {
        ((float4*)out)[q] = v;
    }
}

// ---------------- loc select ----------------
__global__ void __launch_bounds__(128) loc_select_kernel(const __half* __restrict__ h2,
                                                         const __half* __restrict__ WhT,
                                                         const float* __restrict__ bh,
                                                         const int* __restrict__ label,
                                                         float* __restrict__ locp4) {
    int n = blockIdx.x;
    int j = threadIdx.x >> 5, lane = threadIdx.x & 31;
    int row = NCLSP + label[n] * 4 + j;
    const __half2* hv = (const __half2*)(h2 + (size_t)n * HID);
    const __half2* wv = (const __half2*)(WhT + (size_t)row * HID);
    float acc = 0.0f;
    #pragma unroll
    for (int i = 0; i < 16; i++) {
        float2 a = __half22float2(hv[lane + i * 32]);
        float2 b = __half22float2(wv[lane + i * 32]);
        acc += a.x * b.x + a.y * b.y;
    }
    #pragma unroll
    for (int off = 16; off > 0; off >>= 1)
        acc += __shfl_down_sync(0xFFFFFFFF, acc, off);
    if (lane == 0) locp4[n * 4 + j] = acc + bh[row];
}

// ---------------- loss ----------------
__global__ void loss_kernel(const float* __restrict__ head, const float* __restrict__ locp4,
                            const int* __restrict__ label, const float* __restrict__ loc,
                            float* __restrict__ out) {
    __shared__ float red[512];
    int n = threadIdx.x;
    const float* lg = head + (size_t)n * NCLSP;

    float mx = -1e30f;
    for (int j = 0; j < NCLS; j++) mx = fmaxf(mx, lg[j]);
    float s = 0.0f;
    for (int j = 0; j < NCLS; j++) s += expf(lg[j] - mx);
    int lab = label[n];
    float logp = lg[lab] - mx - logf(s);
    float contrib = -logp * (1.0f / (float)NROI);

    if (n < NPOS) {
        #pragma unroll
        for (int j = 0; j < 4; j++) {
            float d = fabsf(locp4[n * 4 + j] - loc[n * 4 + j]);
            float sl1 = (d < 1.0f) ? 0.5f * d * d : d - 0.5f;
            contrib += sl1 * (1.0f / (float)NROI);
        }
    }
    red[n] = contrib;
    __syncthreads();
    for (int stride = 256; stride > 0; stride >>= 1) {
        if (n < stride) red[n] += red[n + stride];
        __syncthreads();
    }
    if (n == 0) out[0] = red[0];
}

// ---------------- launch (two-stream fork/join) ----------------
extern "C" void kernel_launch(void* const* d_in, const int* in_sizes, int n_in,
                              void* d_out, int out_size) {
    const float* P2    = (const float*)d_in[0];
    const float* P3    = (const float*)d_in[1];
    const float* P4    = (const float*)d_in[2];
    const float* P5    = (const float*)d_in[3];
    const float* rois  = (const float*)d_in[4];
    const int*   label = (const int*)  d_in[5];
    const float* loc   = (const float*)d_in[6];
    const float* W1    = (const float*)d_in[7];
    const float* b1    = (const float*)d_in[8];
    const float* W2    = (const float*)d_in[9];
    const float* b2    = (const float*)d_in[10];
    const float* Wcls  = (const float*)d_in[11];
    const float* bcls  = (const float*)d_in[12];
    const float* Wloc  = (const float*)d_in[13];
    const float* bloc  = (const float*)d_in[14];
    float* out = (float*)d_out;

    __half *featT, *xb, *w1t, *w2t, *wht, *h1, *h2;
    float *bh, *head, *locp4, *partb;
    cudaGetSymbolAddress((void**)&featT, g_featT);
    cudaGetSymbolAddress((void**)&xb,    g_x);
    cudaGetSymbolAddress((void**)&w1t,   g_W1T);
    cudaGetSymbolAddress((void**)&w2t,   g_W2T);
    cudaGetSymbolAddress((void**)&wht,   g_WhT);
    cudaGetSymbolAddress((void**)&bh,    g_bh);
    cudaGetSymbolAddress((void**)&h1,    g_h1);
    cudaGetSymbolAddress((void**)&h2,    g_h2);
    cudaGetSymbolAddress((void**)&head,  g_head);
    cudaGetSymbolAddress((void**)&locp4, g_locp4);
    cudaGetSymbolAddress((void**)&partb, g_part);

    static cudaStream_t s2 = nullptr;
    static cudaEvent_t evFork = nullptr, evJoin = nullptr, evFork2 = nullptr, evJoin2 = nullptr;
    if (!s2) {
        cudaStreamCreateWithFlags(&s2, cudaStreamNonBlocking);
        cudaEventCreateWithFlags(&evFork,  cudaEventDisableTiming);
        cudaEventCreateWithFlags(&evJoin,  cudaEventDisableTiming);
        cudaEventCreateWithFlags(&evFork2, cudaEventDisableTiming);
        cudaEventCreateWithFlags(&evJoin2, cudaEventDisableTiming);
        cudaFuncSetAttribute(gemm_hmma_w, cudaFuncAttributeMaxDynamicSharedMemorySize, 73728);
    }

    // ---- fork: weights on s2, features+pool on default ----
    cudaEventRecord(evFork, 0);
    cudaStreamWaitEvent(s2, evFork, 0);

    prep_w<<<3744, 256, 0, s2>>>(W1, W2, Wcls, Wloc, bcls, bloc, w1t, w2t, wht, bh);
    cudaEventRecord(evJoin, s2);

    prep_feat<<<2125, 256>>>(P2, P3, P4, P5, featT);
    pool_v3<<<NROI, 512>>>(rois, (const __half2*)featT, (__half2*)xb);

    cudaStreamWaitEvent(0, evJoin, 0);

    // FC1 (BK=64 wide kernel, split-K = 4)
    gemm_hmma_w<<<dim3(HID / 64, NROI / 128, 4), 256, 73728>>>(xb, w1t, partb, HID, KDIM, KDIM / 4);
    combine_kernel<4, true, true><<<(NROI * HID / 4 + 255) / 256, 256>>>(partb, b1, h1, HID);

    // FC2 (BK=32 proven kernel, split-K = 4)
    gemm_hmma<<<dim3(HID / 64, NROI / 128, 4), 256>>>(h1, w2t, partb, HID, HID, HID / 4);
    combine_kernel<4, true, true><<<(NROI * HID / 4 + 255) / 256, 256>>>(partb, b2, h2, HID);

    // ---- fork: loc_select on s2 parallel with head GEMM ----
    cudaEventRecord(evFork2, 0);
    cudaStreamWaitEvent(s2, evFork2, 0);
    loc_select_kernel<<<NROI, 128, 0, s2>>>(h2, wht, bh, label, locp4);
    cudaEventRecord(evJoin2, s2);

    gemm_direct<<<dim3(NCLSP / 64, NROI / 128), 256>>>(h2, wht, bh, head, NCLSP, HID);

    cudaStreamWaitEvent(0, evJoin2, 0);
    loss_kernel<<<1, 512>>>(head, locp4, label, loc, out);
}